// round 14
// baseline (speedup 1.0000x reference)
#include <cuda_runtime.h>
#include <cuda_bf16.h>
#include <cstdint>

// Problem constants (fixed by the dataset)
#define BB  16
#define TT  128   // txt_T
#define MM  512   // mel_T
#define NC  80    // N_MEL

// k_logprob tiling (round-13 WIN shape)
#define TBLK 32
#define MBLK 128
#define K1_THREADS 128

// Scratch (no cudaMalloc allowed).
__device__ __align__(16) float g_elp[(size_t)BB * MM * TT + 4096]; // exp(lp), [b][m][t]
__device__ float g_alpha[BB];
__device__ unsigned g_cnt = 0;

// smem layout (bytes) for k_logprob — X tile only (62 KB -> 3 blocks/SM)
#define SM_X_OFF  0                             // u64 [NC][64] = 40960
#define SM_WA_OFF (NC * 64 * 8)                 // float2[32][80] = 20480
#define SM_KP_OFF (SM_WA_OFF + TBLK * NC * 8)   // 61440
#define SM_KC_OFF (SM_KP_OFF + TBLK * 4 * 4)    // 61952
#define SM_TOTAL  (SM_KC_OFF + TBLK * 4)        // 62080

// ---- packed f32x2 helpers (sm_103a dual-fp32 pipe; PTX-only) ----
__device__ __forceinline__ void fma2(unsigned long long& d,
                                     unsigned long long a,
                                     unsigned long long b) {
    asm("fma.rn.f32x2 %0, %1, %2, %0;" : "+l"(d) : "l"(a), "l"(b));
}
__device__ __forceinline__ unsigned long long mul2(unsigned long long a,
                                                   unsigned long long b) {
    unsigned long long d;
    asm("mul.rn.f32x2 %0, %1, %2;" : "=l"(d) : "l"(a), "l"(b));
    return d;
}
__device__ __forceinline__ unsigned long long pack2(float lo, float hi) {
    unsigned long long r;
    asm("mov.b64 %0, {%1, %2};" : "=l"(r) : "f"(lo), "f"(hi));
    return r;
}
__device__ __forceinline__ float2 unpack2(unsigned long long v) {
    float lo, hi;
    asm("mov.b64 {%0, %1}, %2;" : "=f"(lo), "=f"(hi) : "l"(v));
    return make_float2(lo, hi);
}

// ---------------------------------------------------------------------------
// Kernel 1: log_prob_matrix + exp(log_prob) scratch. (EXACT round-13 WIN)
// ---------------------------------------------------------------------------
__global__ __launch_bounds__(K1_THREADS)
void k_logprob(const float* __restrict__ ml,     // [B, TT, 2*NC]
               const float* __restrict__ mel,    // [B, NC, MM]
               float* __restrict__ lpm)          // [B, TT, MM] (d_out + 1)
{
    extern __shared__ char sm[];
    unsigned long long* Xs = (unsigned long long*)(sm + SM_X_OFF);  // [NC][64]
    float2* wa = (float2*)(sm + SM_WA_OFF);  // [TBLK][NC] = {w, a}
    float*  kp = (float*) (sm + SM_KP_OFF);  // [TBLK][4]
    float*  kc = (float*) (sm + SM_KC_OFF);  // [TBLK]

    const int b   = blockIdx.z;
    const int t0  = blockIdx.y * TBLK;
    const int m0  = blockIdx.x * MBLK;
    const int tid = threadIdx.x;

    // Phase A: per-t coefficients. thread -> (t = tid/4, c-lane = tid%4)
    {
        const int t  = tid >> 2;
        const int cl = tid & 3;
        const float* row = ml + ((size_t)(b * TT + t0 + t)) * (2 * NC);
        float kpart = 0.f;
#pragma unroll
        for (int i = 0; i < 20; i++) {
            int c = cl + 4 * i;
            float mu = row[c];
            float lv = row[NC + c];
            float w  = __expf(-lv);
            float a  = -2.f * w * mu;
            wa[t * NC + c] = make_float2(w, a);
            kpart += __fmaf_rn(w * mu, mu, lv);
        }
        kp[t * 4 + cl] = kpart;
    }

    // Phase B: melspec tile -> packed x pairs (x only; x^2 computed in-loop)
    for (int lin = tid; lin < NC * 64; lin += K1_THREADS) {
        int c = lin >> 6;
        int p = lin & 63;
        float2 x = ((const float2*)(mel + ((size_t)(b * NC + c)) * MM + m0))[p];
        Xs[c * 64 + p] = pack2(x.x, x.y);
    }
    __syncthreads();

    if (tid < TBLK) {
        kc[tid] = kp[tid*4] + kp[tid*4+1] + kp[tid*4+2] + kp[tid*4+3];
    }
    __syncthreads();

    // Phase C: FFMA2 micro-tile 4t x 4 m-pairs (x^2 via independent MUL2)
    const int tx = tid & 15;     // m-pair lane
    const int ty = tid >> 4;     // t group (4 consecutive t)
    unsigned long long acc[4][4];
#pragma unroll
    for (int tt = 0; tt < 4; tt++)
#pragma unroll
        for (int j = 0; j < 4; j++) acc[tt][j] = 0ull;

#pragma unroll 2
    for (int c = 0; c < NC; c++) {
        unsigned long long x2p[4], xp[4];
#pragma unroll
        for (int j = 0; j < 4; j++) {
            xp[j]  = Xs[c * 64 + tx + 16 * j];
            x2p[j] = mul2(xp[j], xp[j]);
        }
#pragma unroll
        for (int tt = 0; tt < 4; tt++) {
            float2 wv = wa[(4 * ty + tt) * NC + c];
            unsigned long long ww = pack2(wv.x, wv.x);
            unsigned long long aa = pack2(wv.y, wv.y);
#pragma unroll
            for (int j = 0; j < 4; j++) {
                fma2(acc[tt][j], ww, x2p[j]);
                fma2(acc[tt][j], aa, xp[j]);
            }
        }
    }

    // Epilogue
    const float inv = -1.f / (2.f * NC);
    float kt[4];
#pragma unroll
    for (int tt = 0; tt < 4; tt++) kt[tt] = kc[4 * ty + tt];
    const int tg = t0 + 4 * ty;

#pragma unroll
    for (int j = 0; j < 4; j++) {
        const int me = m0 + 2 * (tx + 16 * j);   // even m
        float e0[4], e1[4];
#pragma unroll
        for (int tt = 0; tt < 4; tt++) {
            float2 v = unpack2(acc[tt][j]);
            float lp0 = (v.x + kt[tt]) * inv;
            float lp1 = (v.y + kt[tt]) * inv;
            float* dst = lpm + ((size_t)(b * TT + tg + tt)) * MM + me;
            dst[0] = lp0;          // d_out+1 is only 4B aligned: scalar stores
            dst[1] = lp1;
            e0[tt] = __expf(lp0);
            e1[tt] = __expf(lp1);
        }
        *(float4*)(g_elp + ((size_t)b * MM + me)     * TT + tg) =
            make_float4(e0[0], e0[1], e0[2], e0[3]);
        *(float4*)(g_elp + ((size_t)b * MM + me + 1) * TT + tg) =
            make_float4(e1[0], e1[1], e1[2], e1[3]);
    }
}

// ---------------------------------------------------------------------------
// Kernel 2: probability-domain serial scan. R12 smem ring (WIN) + R5 fused
// double-step (algebra already validated: same rel_err when it passed):
//   q''[t] = A[t](q[t]+q[t-1]) + B[t](q[t-1]+q[t-2]),
//   A[t]=ea[t]*eb[t], B[t]=ea[t-1]*eb[t]   (ea=E[m], eb=E[m+1])
// Boundary shuffles are SOFTWARE-PIPELINED: shfl(n3), shfl(n2) issue as soon
// as n3,n2 exist and are consumed one full double-step later (~20 instr of
// slack -> shfl latency hidden). ea[t-1] at the lane boundary comes from the
// smem ring (off-chain LDS.32; lane 0's value multiplies an exact zero).
// Rescale cadence unchanged (every 16 m-steps, redux), scales s3p/s2p too.
// Tail: proven single-step predicated loop.
// ---------------------------------------------------------------------------
__global__ __launch_bounds__(32)
void k_scan(const float* __restrict__ out_base,  // d_out (out[0]=loss, +1=lpm)
            const int* __restrict__ tlen,
            const int* __restrict__ mlen)
{
    __shared__ __align__(16) float SE[64 * 128];  // 2 buffers x 32 rows x 128 t

    const int b    = blockIdx.x;
    const int lane = threadIdx.x;
    const float* Eb = g_elp + (size_t)b * MM * TT;   // [m][128]

    const int mel_len = mlen[b];
    const int txt_len = tlen[b];
    const int last    = mel_len - 1;          // >= 255 for this dataset

    float q0 = (lane == 0) ? 1.f : 0.f;
    float q1 = 0.f, q2 = 0.f, q3 = 0.f;
    float s3p = 0.f, s2p = 0.f;               // pipelined boundary values
    const bool isL0 = (lane == 0);
    const float L0 = out_base[1 + (size_t)b * TT * MM];  // lp[b,0,0]
    int kTot = 0;
    const int tb = isL0 ? 0 : (4 * lane - 1); // boundary t-index (lane0 dummy)

    const uint32_t se_base =
        (uint32_t)__cvta_generic_to_shared(SE) + lane * 16;

#define ISSUE_CHUNK(kk)                                               \
    {                                                                 \
        uint32_t d0 = se_base + ((kk) & 1) * 16384;                   \
        _Pragma("unroll")                                             \
        for (int s = 0; s < 32; s++) {                                \
            int row = 1 + 32 * (kk) + s;                              \
            if (row > MM - 1) row = MM - 1;                           \
            const float* src = Eb + (size_t)row * TT + lane * 4;      \
            asm volatile("cp.async.cg.shared.global [%0], [%1], 16;"  \
                         :: "r"(d0 + s * 512), "l"(src));             \
        }                                                             \
        asm volatile("cp.async.commit_group;");                       \
    }

    // exact 2^k rescale via redux; scales pipelined s3p/s2p too
#define RESCALE_R()                                               \
    {                                                             \
        float mxq = fmaxf(fmaxf(q0, q1), fmaxf(q2, q3));          \
        unsigned mb;                                              \
        asm("redux.sync.max.u32 %0, %1, 0xffffffff;"              \
            : "=r"(mb) : "r"(__float_as_uint(mxq)));              \
        if (mb != 0u) {                                           \
            int eb = (int)(mb >> 23) & 0xff;                      \
            float sc = __int_as_float((254 - eb) << 23);          \
            q0 *= sc; q1 *= sc; q2 *= sc; q3 *= sc;               \
            s3p *= sc; s2p *= sc;                                 \
            kTot += eb - 127;                                     \
        }                                                         \
    }

    // tail step (proven): self-contained shfl, select freeze
#define STEPQ_PRED(e, act)                                        \
    {                                                             \
        float tp = __shfl_up_sync(0xffffffffu, q3, 1);            \
        if (isL0) tp = 0.f;                                       \
        float n0 = (q0 + tp) * (e).x;                             \
        float n1 = (q1 + q0) * (e).y;                             \
        float n2 = (q2 + q1) * (e).z;                             \
        float n3 = (q3 + q2) * (e).w;                             \
        q0 = (act) ? n0 : q0;                                     \
        q1 = (act) ? n1 : q1;                                     \
        q2 = (act) ? n2 : q2;                                     \
        q3 = (act) ? n3 : q3;                                     \
    }

    ISSUE_CHUNK(0);
    ISSUE_CHUNK(1);

    int m = 1, k = 0;
    while (m + 31 <= last) {
        asm volatile("cp.async.wait_group 1;");   // chunk k landed
        const float* sbf = SE + (k & 1) * 4096;
        // preload double-step 0 of this chunk
        float4 ea = *(const float4*)(sbf + 4 * lane);
        float4 eb = *(const float4*)(sbf + 128 + 4 * lane);
        float  em = sbf[tb];
#pragma unroll
        for (int i = 0; i < 16; i++) {            // 16 double-steps = 32 m
            float4 ea_n, eb_n; float em_n;
            if (i < 15) {                         // prefetch next double-step
                ea_n = *(const float4*)(sbf + (2 * i + 2) * 128 + 4 * lane);
                eb_n = *(const float4*)(sbf + (2 * i + 3) * 128 + 4 * lane);
                em_n = sbf[(2 * i + 2) * 128 + tb];
            }
            // coefficients (off the q-chain)
            float A0 = ea.x * eb.x, A1 = ea.y * eb.y;
            float A2 = ea.z * eb.z, A3 = ea.w * eb.w;
            float B0 = em   * eb.x, B1 = ea.x * eb.y;
            float B2 = ea.y * eb.z, B3 = ea.z * eb.w;
            float t32 = q3 + q2, t21 = q2 + q1, t10 = q1 + q0;
            float t0s = q0 + s3p, tss = s3p + s2p;
            float n3 = __fmaf_rn(A3, t32, B3 * t21);
            float n2 = __fmaf_rn(A2, t21, B2 * t10);
            // next double-step's boundary values: issue shuffles NOW
            float u3 = __shfl_up_sync(0xffffffffu, n3, 1);
            float u2 = __shfl_up_sync(0xffffffffu, n2, 1);
            float n1 = __fmaf_rn(A1, t10, B1 * t0s);
            float n0 = __fmaf_rn(A0, t0s, B0 * tss);
            q3 = n3; q2 = n2; q1 = n1; q0 = n0;
            s3p = isL0 ? 0.f : u3;
            s2p = isL0 ? 0.f : u2;
            if (i < 15) { ea = ea_n; eb = eb_n; em = em_n; }
            if (i == 7) RESCALE_R();              // after 16 m-steps
        }
        ISSUE_CHUNK(k + 2);
        RESCALE_R();                              // after 32 m-steps
        m += 32; k++;
    }

    // tail: <=31 steps, single-step predicated; discards s3p/s2p (recomputed)
    asm volatile("cp.async.wait_group 0;");
    {
        const float* sb = SE + (k & 1) * 4096 + lane * 4;
#pragma unroll
        for (int s = 0; s < 32; s++) {
            float4 e = *(const float4*)(sb + s * 128);
            STEPQ_PRED(e, (m + s) <= last);
        }
    }

#undef ISSUE_CHUNK
#undef RESCALE_R
#undef STEPQ_PRED

    // extract alpha_last, fold loss reduction (proven ticket scheme)
    {
        const int idx = txt_len - 1;
        const int sel = idx & 3;
        float v = (sel == 0) ? q0 : (sel == 1) ? q1 : (sel == 2) ? q2 : q3;
        v = __shfl_sync(0xffffffffu, v, idx >> 2);
        if (lane == 0) {
            float alpha = __logf(v) + (float)kTot * 0.69314718055994531f + L0;
            g_alpha[b] = alpha / (float)mel_len;
            __threadfence();
            unsigned ticket = atomicAdd(&g_cnt, 1u);
            if (ticket == BB - 1) {
                __threadfence();
                float s = 0.f;
#pragma unroll
                for (int i = 0; i < BB; i++)
                    s += ((volatile float*)g_alpha)[i];
                ((float*)out_base)[0] = -s * (1.f / BB);
                g_cnt = 0;   // reset for next graph replay
            }
        }
    }
}

// ---------------------------------------------------------------------------
extern "C" void kernel_launch(void* const* d_in, const int* in_sizes, int n_in,
                              void* d_out, int out_size)
{
    const float* ml  = (const float*)d_in[0];   // mu_logvar [16,128,160]
    const float* mel = (const float*)d_in[1];   // melspec   [16,80,512]
    const int*   tl  = (const int*)d_in[2];     // text_lengths [16]
    const int*   mll = (const int*)d_in[3];     // mel_lengths  [16]
    float* out = (float*)d_out;                 // [0]=loss, [1..]=log_prob_matrix

    cudaFuncSetAttribute(k_logprob,
                         cudaFuncAttributeMaxDynamicSharedMemorySize, SM_TOTAL);

    k_logprob<<<dim3(MM / MBLK, TT / TBLK, BB), K1_THREADS, SM_TOTAL>>>(
        ml, mel, out + 1);
    k_scan<<<BB, 32>>>(out, tl, mll);
}